// round 1
// baseline (speedup 1.0000x reference)
#include <cuda_runtime.h>

#define N_NODES 50000
#define N_EDGES 800000
#define D_IN    256
#define D_HID   128
#define D_OUT   40

// ---- persistent scratch (no allocations allowed) ----
__device__ float g_degout[N_NODES];
__device__ float g_degin [N_NODES];
__device__ float g_nsrc  [N_NODES];
__device__ float g_ndst  [N_NODES];
__device__ float g_h0  [(size_t)N_NODES * D_HID];   // (x*nsrc)@W1, later reused for mid features
__device__ float g_agg1[(size_t)N_NODES * D_HID];   // scatter accumulator layer 1
__device__ float g_h1  [(size_t)N_NODES * D_OUT];   // (mid)@W2

// ---------------------------------------------------------------------------
// zero everything that gets atomically accumulated (+ d_out, poisoned by harness)
__global__ void k_zero(float* __restrict__ out) {
    int i = blockIdx.x * blockDim.x + threadIdx.x;
    if (i < N_NODES * D_HID) g_agg1[i] = 0.0f;
    if (i < N_NODES * D_OUT) out[i] = 0.0f;
    if (i < N_NODES) { g_degout[i] = 0.0f; g_degin[i] = 0.0f; }
}

// degree counting
__global__ void k_deg(const int* __restrict__ src, const int* __restrict__ dst) {
    int i = blockIdx.x * blockDim.x + threadIdx.x;
    if (i < N_EDGES) {
        atomicAdd(&g_degout[src[i]], 1.0f);
        atomicAdd(&g_degin [dst[i]], 1.0f);
    }
}

// norms
__global__ void k_norm() {
    int i = blockIdx.x * blockDim.x + threadIdx.x;
    if (i < N_NODES) {
        g_nsrc[i] = rsqrtf(fmaxf(g_degout[i], 1.0f));
        g_ndst[i] = rsqrtf(fmaxf(g_degin [i], 1.0f));
    }
}

// ---------------------------------------------------------------------------
// GEMM1: g_h0[50000,128] = (x * nsrc[:,None]) @ W1[256,128]
// tile: BM=64, BN=128, BK=32, 256 threads, each thread 4 rows x 8 cols
__global__ __launch_bounds__(256) void k_gemm1(const float* __restrict__ x,
                                               const float* __restrict__ W1) {
    __shared__ float xs[64][33];
    __shared__ float ws[32][128];
    const int tid = threadIdx.x;
    const int tx = tid & 15;      // col group (8 cols each)
    const int ty = tid >> 4;      // row group (4 rows each)
    const int m0 = blockIdx.x * 64;

    float acc[4][8];
#pragma unroll
    for (int i = 0; i < 4; i++)
#pragma unroll
        for (int j = 0; j < 8; j++) acc[i][j] = 0.0f;

    for (int k0 = 0; k0 < D_IN; k0 += 32) {
        // load x tile 64x32 (scaled by nsrc)
#pragma unroll
        for (int t = 0; t < 8; t++) {
            int idx = tid + t * 256;
            int r = idx >> 5, c = idx & 31;
            int row = m0 + r;
            float v = 0.0f;
            if (row < N_NODES) v = x[(size_t)row * D_IN + k0 + c] * g_nsrc[row];
            xs[r][c] = v;
        }
        // load W1 tile 32x128
#pragma unroll
        for (int t = 0; t < 16; t++) {
            int idx = tid + t * 256;
            int r = idx >> 7, c = idx & 127;
            ws[r][c] = W1[(size_t)(k0 + r) * D_HID + c];
        }
        __syncthreads();
#pragma unroll
        for (int kk = 0; kk < 32; kk++) {
            float xv[4], wv[8];
#pragma unroll
            for (int i = 0; i < 4; i++) xv[i] = xs[ty * 4 + i][kk];
#pragma unroll
            for (int j = 0; j < 8; j++) wv[j] = ws[kk][tx * 8 + j];
#pragma unroll
            for (int i = 0; i < 4; i++)
#pragma unroll
                for (int j = 0; j < 8; j++) acc[i][j] += xv[i] * wv[j];
        }
        __syncthreads();
    }
#pragma unroll
    for (int i = 0; i < 4; i++) {
        int row = m0 + ty * 4 + i;
        if (row < N_NODES) {
#pragma unroll
            for (int j = 0; j < 8; j++)
                g_h0[(size_t)row * D_HID + tx * 8 + j] = acc[i][j];
        }
    }
}

// ---------------------------------------------------------------------------
// scatter layer1: agg1[dst] += h0[src]  (128 floats per edge)
__global__ void k_scat1(const int* __restrict__ src, const int* __restrict__ dst) {
    long long i = (long long)blockIdx.x * blockDim.x + threadIdx.x;
    if (i < (long long)N_EDGES * D_HID) {
        int e = (int)(i >> 7);
        int c = (int)(i & 127);
        int s = __ldg(&src[e]);
        int d = __ldg(&dst[e]);
        atomicAdd(&g_agg1[(size_t)d * D_HID + c], g_h0[(size_t)s * D_HID + c]);
    }
}

// mid: h0 <- relu(agg1 * ndst + b1) * nsrc   (pre-scaled input for layer 2)
__global__ void k_mid(const float* __restrict__ b1) {
    int i = blockIdx.x * blockDim.x + threadIdx.x;
    if (i < N_NODES * D_HID) {
        int row = i >> 7;
        int c = i & 127;
        float v = g_agg1[i] * g_ndst[row] + __ldg(&b1[c]);
        g_h0[i] = fmaxf(v, 0.0f) * g_nsrc[row];
    }
}

// ---------------------------------------------------------------------------
// GEMM2: g_h1[50000,40] = g_h0(mid)[50000,128] @ W2[128,40]
// block: 32 rows, 256 threads, each thread 5 outputs; W2 fully in smem
__global__ __launch_bounds__(256) void k_gemm2(const float* __restrict__ W2) {
    __shared__ float w2s[D_HID * D_OUT];   // 20 KB
    __shared__ float hs[32][129];          // ~16.5 KB
    const int tid = threadIdx.x;
    const int m0 = blockIdx.x * 32;

    for (int i = tid; i < D_HID * D_OUT; i += 256) w2s[i] = W2[i];
#pragma unroll
    for (int t = 0; t < 16; t++) {
        int idx = tid + t * 256;
        int r = idx >> 7, c = idx & 127;
        int row = m0 + r;
        hs[r][c] = (row < N_NODES) ? g_h0[(size_t)row * D_HID + c] : 0.0f;
    }
    __syncthreads();

    float acc[5] = {0.f, 0.f, 0.f, 0.f, 0.f};
    int rr[5], cc[5];
#pragma unroll
    for (int t = 0; t < 5; t++) {
        int o = tid + t * 256;
        rr[t] = o / D_OUT;
        cc[t] = o - rr[t] * D_OUT;
    }
#pragma unroll 4
    for (int k = 0; k < D_HID; k++) {
#pragma unroll
        for (int t = 0; t < 5; t++)
            acc[t] += hs[rr[t]][k] * w2s[k * D_OUT + cc[t]];
    }
#pragma unroll
    for (int t = 0; t < 5; t++) {
        int row = m0 + rr[t];
        if (row < N_NODES) g_h1[(size_t)row * D_OUT + cc[t]] = acc[t];
    }
}

// scatter layer2: out[dst] += h1[src]  (40 floats per edge)
__global__ void k_scat2(const int* __restrict__ src, const int* __restrict__ dst,
                        float* __restrict__ out) {
    long long i = (long long)blockIdx.x * blockDim.x + threadIdx.x;
    if (i < (long long)N_EDGES * D_OUT) {
        int e = (int)(i / D_OUT);
        int c = (int)(i - (long long)e * D_OUT);
        int s = __ldg(&src[e]);
        int d = __ldg(&dst[e]);
        atomicAdd(&out[(size_t)d * D_OUT + c], g_h1[(size_t)s * D_OUT + c]);
    }
}

// finalize: out = out * ndst + b2
__global__ void k_fin(float* __restrict__ out, const float* __restrict__ b2) {
    int i = blockIdx.x * blockDim.x + threadIdx.x;
    if (i < N_NODES * D_OUT) {
        int row = i / D_OUT;
        int c = i - row * D_OUT;
        out[i] = out[i] * g_ndst[row] + __ldg(&b2[c]);
    }
}

// ---------------------------------------------------------------------------
extern "C" void kernel_launch(void* const* d_in, const int* in_sizes, int n_in,
                              void* d_out, int out_size) {
    const float* x   = (const float*)d_in[0];
    const float* W1  = (const float*)d_in[1];
    const float* b1  = (const float*)d_in[2];
    const float* W2  = (const float*)d_in[3];
    const float* b2  = (const float*)d_in[4];
    const int* esrc  = (const int*)d_in[5];
    const int* edst  = (const int*)d_in[6];
    float* out = (float*)d_out;

    const int T = 256;

    // zero accumulators + output
    k_zero<<<(N_NODES * D_HID + T - 1) / T, T>>>(out);
    // degrees + norms
    k_deg<<<(N_EDGES + T - 1) / T, T>>>(esrc, edst);
    k_norm<<<(N_NODES + T - 1) / T, T>>>();
    // layer 1
    k_gemm1<<<(N_NODES + 63) / 64, 256>>>(x, W1);
    {
        long long work = (long long)N_EDGES * D_HID;
        int blocks = (int)((work + T - 1) / T);
        k_scat1<<<blocks, T>>>(esrc, edst);
    }
    k_mid<<<(N_NODES * D_HID + T - 1) / T, T>>>(b1);
    // layer 2
    k_gemm2<<<(N_NODES + 31) / 32, 256>>>(W2);
    {
        long long work = (long long)N_EDGES * D_OUT;
        int blocks = (int)((work + T - 1) / T);
        k_scat2<<<blocks, T>>>(esrc, edst, out);
    }
    k_fin<<<(N_NODES * D_OUT + T - 1) / T, T>>>(out, b2);
}

// round 2
// speedup vs baseline: 1.8978x; 1.8978x over previous
#include <cuda_runtime.h>

#define N_NODES 50000
#define N_EDGES 800000
#define D_IN    256
#define D_HID   128
#define D_OUT   40

// ---- persistent scratch (no allocations allowed) ----
__device__ int   g_cnt_in [N_NODES];
__device__ int   g_cnt_out[N_NODES];
__device__ int   g_off    [N_NODES + 1];
__device__ int   g_cursor [N_NODES];
__device__ int   g_eidx   [N_EDGES];           // src indices grouped by dst (CSR)
__device__ float g_nsrc   [N_NODES];
__device__ float g_ndst   [N_NODES];
__device__ float g_h0  [(size_t)N_NODES * D_HID];   // (x*nsrc)@W1
__device__ float g_mid [(size_t)N_NODES * D_HID];   // relu(agg*ndst+b1)*nsrc
__device__ float g_h1  [(size_t)N_NODES * D_OUT];   // mid@W2

// ---------------------------------------------------------------------------
__global__ void k_init() {
    int i = blockIdx.x * blockDim.x + threadIdx.x;
    if (i < N_NODES) { g_cnt_in[i] = 0; g_cnt_out[i] = 0; }
}

__global__ void k_hist(const int* __restrict__ src, const int* __restrict__ dst) {
    int i = blockIdx.x * blockDim.x + threadIdx.x;
    if (i < N_EDGES) {
        atomicAdd(&g_cnt_out[src[i]], 1);
        atomicAdd(&g_cnt_in [dst[i]], 1);
    }
}

__global__ void k_norm() {
    int i = blockIdx.x * blockDim.x + threadIdx.x;
    if (i < N_NODES) {
        g_nsrc[i] = rsqrtf(fmaxf((float)g_cnt_out[i], 1.0f));
        g_ndst[i] = rsqrtf(fmaxf((float)g_cnt_in [i], 1.0f));
    }
}

// single-block exclusive scan of g_cnt_in -> g_off / g_cursor
__global__ __launch_bounds__(1024) void k_scan() {
    __shared__ int sums[1024];
    const int CH = (N_NODES + 1023) / 1024;   // 49
    int t = threadIdx.x;
    int base = t * CH;
    int local = 0;
    for (int j = 0; j < CH; j++) {
        int idx = base + j;
        if (idx < N_NODES) local += g_cnt_in[idx];
    }
    sums[t] = local;
    __syncthreads();
    for (int off = 1; off < 1024; off <<= 1) {
        int v = 0;
        if (t >= off) v = sums[t - off];
        __syncthreads();
        if (t >= off) sums[t] += v;
        __syncthreads();
    }
    int run = (t > 0) ? sums[t - 1] : 0;
    for (int j = 0; j < CH; j++) {
        int idx = base + j;
        if (idx < N_NODES) {
            g_off[idx] = run;
            g_cursor[idx] = run;
            run += g_cnt_in[idx];
        }
    }
    if (t == 1023) g_off[N_NODES] = N_EDGES;
}

__global__ void k_fill(const int* __restrict__ src, const int* __restrict__ dst) {
    int i = blockIdx.x * blockDim.x + threadIdx.x;
    if (i < N_EDGES) {
        int d = dst[i];
        int pos = atomicAdd(&g_cursor[d], 1);
        g_eidx[pos] = src[i];
    }
}

// ---------------------------------------------------------------------------
// GEMM1: g_h0[50000,128] = (x * nsrc[:,None]) @ W1[256,128]
// 128x128x16 tile, 256 threads, 8x8 micro-tile, float4 everywhere.
__global__ __launch_bounds__(256) void k_gemm1(const float* __restrict__ x,
                                               const float* __restrict__ W1) {
    __shared__ float As[16][132];   // transposed A tile [k][row]
    __shared__ float Bs[16][128];   // [k][col]
    const int tid = threadIdx.x;
    const int tx = tid & 15;        // 0..15 -> 8 cols each
    const int ty = tid >> 4;        // 0..15 -> 8 rows each
    const int m0 = blockIdx.x * 128;

    float acc[8][8];
#pragma unroll
    for (int i = 0; i < 8; i++)
#pragma unroll
        for (int j = 0; j < 8; j++) acc[i][j] = 0.0f;

    for (int k0 = 0; k0 < D_IN; k0 += 16) {
        // load A tile (128 rows x 16 k), scaled by nsrc, stored transposed
#pragma unroll
        for (int t = 0; t < 2; t++) {
            int idx = tid + t * 256;      // 0..511
            int r = idx >> 2;             // row 0..127
            int kq = idx & 3;             // float4 within the 16 k's
            int row = m0 + r;
            float4 v = make_float4(0.f, 0.f, 0.f, 0.f);
            float s = 0.0f;
            if (row < N_NODES) {
                v = reinterpret_cast<const float4*>(x + (size_t)row * D_IN + k0)[kq];
                s = g_nsrc[row];
            }
            As[kq * 4 + 0][r] = v.x * s;
            As[kq * 4 + 1][r] = v.y * s;
            As[kq * 4 + 2][r] = v.z * s;
            As[kq * 4 + 3][r] = v.w * s;
        }
        // load B tile (16 k x 128 cols)
#pragma unroll
        for (int t = 0; t < 2; t++) {
            int idx = tid + t * 256;      // 0..511
            int r = idx >> 5;             // k row 0..15
            int c4 = idx & 31;            // float4 col
            float4 w = reinterpret_cast<const float4*>(W1 + (size_t)(k0 + r) * D_HID)[c4];
            reinterpret_cast<float4*>(&Bs[r][c4 * 4])[0] = w;
        }
        __syncthreads();
#pragma unroll
        for (int kk = 0; kk < 16; kk++) {
            float a[8], b[8];
#pragma unroll
            for (int i = 0; i < 8; i++) a[i] = As[kk][ty * 8 + i];
#pragma unroll
            for (int j = 0; j < 8; j++) b[j] = Bs[kk][tx * 8 + j];
#pragma unroll
            for (int i = 0; i < 8; i++)
#pragma unroll
                for (int j = 0; j < 8; j++) acc[i][j] += a[i] * b[j];
        }
        __syncthreads();
    }
#pragma unroll
    for (int i = 0; i < 8; i++) {
        int row = m0 + ty * 8 + i;
        if (row < N_NODES) {
            float4 v0 = make_float4(acc[i][0], acc[i][1], acc[i][2], acc[i][3]);
            float4 v1 = make_float4(acc[i][4], acc[i][5], acc[i][6], acc[i][7]);
            float4* p = reinterpret_cast<float4*>(g_h0 + (size_t)row * D_HID + tx * 8);
            p[0] = v0;
            p[1] = v1;
        }
    }
}

// ---------------------------------------------------------------------------
// gather-aggregate layer 1 (fused with mid transform):
// mid[n] = relu( (sum_{e: dst=n} h0[src_e]) * ndst[n] + b1 ) * nsrc[n]
__global__ __launch_bounds__(128) void k_gather1(const float* __restrict__ b1) {
    int node = blockIdx.x;
    int c = threadIdx.x;
    int beg = g_off[node], end = g_off[node + 1];
    float acc0 = 0.0f, acc1 = 0.0f;
    int i = beg;
    for (; i + 1 < end; i += 2) {
        int s0 = __ldg(&g_eidx[i]);
        int s1 = __ldg(&g_eidx[i + 1]);
        acc0 += g_h0[(size_t)s0 * D_HID + c];
        acc1 += g_h0[(size_t)s1 * D_HID + c];
    }
    if (i < end) acc0 += g_h0[(size_t)__ldg(&g_eidx[i]) * D_HID + c];
    float v = (acc0 + acc1) * g_ndst[node] + __ldg(&b1[c]);
    g_mid[(size_t)node * D_HID + c] = fmaxf(v, 0.0f) * g_nsrc[node];
}

// ---------------------------------------------------------------------------
// GEMM2: g_h1[50000,40] = g_mid[50000,128] @ W2[128,40]
__global__ __launch_bounds__(256) void k_gemm2(const float* __restrict__ W2) {
    __shared__ float w2s[D_HID * D_OUT];   // 20 KB
    __shared__ float hs[32][129];
    const int tid = threadIdx.x;
    const int m0 = blockIdx.x * 32;

    for (int i = tid; i < D_HID * D_OUT; i += 256) w2s[i] = W2[i];
#pragma unroll
    for (int t = 0; t < 16; t++) {
        int idx = tid + t * 256;
        int r = idx >> 7, c = idx & 127;
        int row = m0 + r;
        hs[r][c] = (row < N_NODES) ? g_mid[(size_t)row * D_HID + c] : 0.0f;
    }
    __syncthreads();

    float acc[5] = {0.f, 0.f, 0.f, 0.f, 0.f};
    int rr[5], cc[5];
#pragma unroll
    for (int t = 0; t < 5; t++) {
        int o = tid + t * 256;
        rr[t] = o / D_OUT;
        cc[t] = o - rr[t] * D_OUT;
    }
#pragma unroll 4
    for (int k = 0; k < D_HID; k++) {
#pragma unroll
        for (int t = 0; t < 5; t++)
            acc[t] += hs[rr[t]][k] * w2s[k * D_OUT + cc[t]];
    }
#pragma unroll
    for (int t = 0; t < 5; t++) {
        int row = m0 + rr[t];
        if (row < N_NODES) g_h1[(size_t)row * D_OUT + cc[t]] = acc[t];
    }
}

// gather-aggregate layer 2 (fused with final bias/norm):
// out[n] = (sum_{e: dst=n} h1[src_e]) * ndst[n] + b2
__global__ __launch_bounds__(64) void k_gather2(float* __restrict__ out,
                                                const float* __restrict__ b2) {
    int node = blockIdx.x;
    int c = threadIdx.x;
    if (c >= D_OUT) return;
    int beg = g_off[node], end = g_off[node + 1];
    float acc0 = 0.0f, acc1 = 0.0f;
    int i = beg;
    for (; i + 1 < end; i += 2) {
        int s0 = __ldg(&g_eidx[i]);
        int s1 = __ldg(&g_eidx[i + 1]);
        acc0 += g_h1[(size_t)s0 * D_OUT + c];
        acc1 += g_h1[(size_t)s1 * D_OUT + c];
    }
    if (i < end) acc0 += g_h1[(size_t)__ldg(&g_eidx[i]) * D_OUT + c];
    out[(size_t)node * D_OUT + c] = (acc0 + acc1) * g_ndst[node] + __ldg(&b2[c]);
}

// ---------------------------------------------------------------------------
extern "C" void kernel_launch(void* const* d_in, const int* in_sizes, int n_in,
                              void* d_out, int out_size) {
    const float* x   = (const float*)d_in[0];
    const float* W1  = (const float*)d_in[1];
    const float* b1  = (const float*)d_in[2];
    const float* W2  = (const float*)d_in[3];
    const float* b2  = (const float*)d_in[4];
    const int* esrc  = (const int*)d_in[5];
    const int* edst  = (const int*)d_in[6];
    float* out = (float*)d_out;

    const int T = 256;

    // CSR build + norms
    k_init<<<(N_NODES + T - 1) / T, T>>>();
    k_hist<<<(N_EDGES + T - 1) / T, T>>>(esrc, edst);
    k_norm<<<(N_NODES + T - 1) / T, T>>>();
    k_scan<<<1, 1024>>>();
    k_fill<<<(N_EDGES + T - 1) / T, T>>>(esrc, edst);

    // layer 1
    k_gemm1<<<(N_NODES + 127) / 128, 256>>>(x, W1);
    k_gather1<<<N_NODES, 128>>>(b1);

    // layer 2
    k_gemm2<<<(N_NODES + 31) / 32, 256>>>(W2);
    k_gather2<<<N_NODES, 64>>>(out, b2);
}

// round 3
// speedup vs baseline: 2.3849x; 1.2566x over previous
#include <cuda_runtime.h>

#define N_NODES 50000
#define N_EDGES 800000
#define D_IN    256
#define D_HID   128
#define D_OUT   40

#define SCAN_BLK 256
#define N_PART   ((N_NODES + SCAN_BLK - 1) / SCAN_BLK)   // 196

// ---- persistent scratch (no allocations allowed) ----
__device__ int   g_cnt_in [N_NODES];
__device__ int   g_cnt_out[N_NODES];
__device__ int   g_part   [N_PART];
__device__ int   g_pscan  [N_PART];
__device__ int   g_off    [N_NODES + 1];
__device__ int   g_cursor [N_NODES];
__device__ int   g_eidx   [N_EDGES];           // src indices grouped by dst (CSR)
__device__ float g_nsrc   [N_NODES];
__device__ float g_ndst   [N_NODES];
__device__ float g_h0  [(size_t)N_NODES * D_HID];   // (x*nsrc)@W1
__device__ float g_mid [(size_t)N_NODES * D_HID];   // relu(agg*ndst+b1)*nsrc
__device__ float g_h1  [(size_t)N_NODES * D_OUT];   // mid@W2

// ---------------------------------------------------------------------------
__global__ void k_init() {
    int i = blockIdx.x * blockDim.x + threadIdx.x;
    if (i < N_NODES) { g_cnt_in[i] = 0; g_cnt_out[i] = 0; }
}

__global__ void k_hist(const int* __restrict__ src, const int* __restrict__ dst) {
    int i = blockIdx.x * blockDim.x + threadIdx.x;
    if (i < N_EDGES) {
        atomicAdd(&g_cnt_out[src[i]], 1);
        atomicAdd(&g_cnt_in [dst[i]], 1);
    }
}

// phase 1: per-block sums of cnt_in
__global__ __launch_bounds__(SCAN_BLK) void k_part() {
    __shared__ int sh[SCAN_BLK];
    int idx = blockIdx.x * SCAN_BLK + threadIdx.x;
    int v = (idx < N_NODES) ? g_cnt_in[idx] : 0;
    sh[threadIdx.x] = v;
    __syncthreads();
    for (int off = SCAN_BLK / 2; off > 0; off >>= 1) {
        if (threadIdx.x < off) sh[threadIdx.x] += sh[threadIdx.x + off];
        __syncthreads();
    }
    if (threadIdx.x == 0) g_part[blockIdx.x] = sh[0];
}

// phase 2: exclusive scan of the N_PART partials (single small block)
__global__ __launch_bounds__(256) void k_scanpart() {
    __shared__ int sh[256];
    int t = threadIdx.x;
    sh[t] = (t < N_PART) ? g_part[t] : 0;
    __syncthreads();
    for (int off = 1; off < 256; off <<= 1) {
        int v = 0;
        if (t >= off) v = sh[t - off];
        __syncthreads();
        if (t >= off) sh[t] += v;
        __syncthreads();
    }
    if (t < N_PART) g_pscan[t] = (t > 0) ? sh[t - 1] : 0;   // exclusive
    if (t == 0) g_off[N_NODES] = N_EDGES;
}

// phase 3: in-block exclusive scan + block offset -> g_off/g_cursor; fused norms
__global__ __launch_bounds__(SCAN_BLK) void k_apply() {
    __shared__ int sh[SCAN_BLK];
    int t = threadIdx.x;
    int idx = blockIdx.x * SCAN_BLK + t;
    int cin = (idx < N_NODES) ? g_cnt_in[idx] : 0;
    sh[t] = cin;
    __syncthreads();
    for (int off = 1; off < SCAN_BLK; off <<= 1) {
        int v = 0;
        if (t >= off) v = sh[t - off];
        __syncthreads();
        if (t >= off) sh[t] += v;
        __syncthreads();
    }
    if (idx < N_NODES) {
        int excl = sh[t] - cin + g_pscan[blockIdx.x];
        g_off[idx] = excl;
        g_cursor[idx] = excl;
        g_nsrc[idx] = rsqrtf(fmaxf((float)g_cnt_out[idx], 1.0f));
        g_ndst[idx] = rsqrtf(fmaxf((float)cin, 1.0f));
    }
}

__global__ void k_fill(const int* __restrict__ src, const int* __restrict__ dst) {
    int i = blockIdx.x * blockDim.x + threadIdx.x;
    if (i < N_EDGES) {
        int d = dst[i];
        int pos = atomicAdd(&g_cursor[d], 1);
        g_eidx[pos] = src[i];
    }
}

// ---------------------------------------------------------------------------
// GEMM1: g_h0[50000,128] = (x * nsrc[:,None]) @ W1[256,128]
// 128x128x16 tile, 256 threads, 8x8 micro-tile, float4 everywhere.
__global__ __launch_bounds__(256) void k_gemm1(const float* __restrict__ x,
                                               const float* __restrict__ W1) {
    __shared__ float As[16][132];   // transposed A tile [k][row]
    __shared__ float Bs[16][128];   // [k][col]
    const int tid = threadIdx.x;
    const int tx = tid & 15;        // 0..15 -> 8 cols each
    const int ty = tid >> 4;        // 0..15 -> 8 rows each
    const int m0 = blockIdx.x * 128;

    float acc[8][8];
#pragma unroll
    for (int i = 0; i < 8; i++)
#pragma unroll
        for (int j = 0; j < 8; j++) acc[i][j] = 0.0f;

    for (int k0 = 0; k0 < D_IN; k0 += 16) {
        // load A tile (128 rows x 16 k), scaled by nsrc, stored transposed
#pragma unroll
        for (int t = 0; t < 2; t++) {
            int idx = tid + t * 256;      // 0..511
            int r = idx >> 2;             // row 0..127
            int kq = idx & 3;             // float4 within the 16 k's
            int row = m0 + r;
            float4 v = make_float4(0.f, 0.f, 0.f, 0.f);
            float s = 0.0f;
            if (row < N_NODES) {
                v = reinterpret_cast<const float4*>(x + (size_t)row * D_IN + k0)[kq];
                s = g_nsrc[row];
            }
            As[kq * 4 + 0][r] = v.x * s;
            As[kq * 4 + 1][r] = v.y * s;
            As[kq * 4 + 2][r] = v.z * s;
            As[kq * 4 + 3][r] = v.w * s;
        }
        // load B tile (16 k x 128 cols)
#pragma unroll
        for (int t = 0; t < 2; t++) {
            int idx = tid + t * 256;      // 0..511
            int r = idx >> 5;             // k row 0..15
            int c4 = idx & 31;            // float4 col
            float4 w = reinterpret_cast<const float4*>(W1 + (size_t)(k0 + r) * D_HID)[c4];
            reinterpret_cast<float4*>(&Bs[r][c4 * 4])[0] = w;
        }
        __syncthreads();
#pragma unroll
        for (int kk = 0; kk < 16; kk++) {
            float a[8], b[8];
#pragma unroll
            for (int i = 0; i < 8; i++) a[i] = As[kk][ty * 8 + i];
#pragma unroll
            for (int j = 0; j < 8; j++) b[j] = Bs[kk][tx * 8 + j];
#pragma unroll
            for (int i = 0; i < 8; i++)
#pragma unroll
                for (int j = 0; j < 8; j++) acc[i][j] += a[i] * b[j];
        }
        __syncthreads();
    }
#pragma unroll
    for (int i = 0; i < 8; i++) {
        int row = m0 + ty * 8 + i;
        if (row < N_NODES) {
            float4 v0 = make_float4(acc[i][0], acc[i][1], acc[i][2], acc[i][3]);
            float4 v1 = make_float4(acc[i][4], acc[i][5], acc[i][6], acc[i][7]);
            float4* p = reinterpret_cast<float4*>(g_h0 + (size_t)row * D_HID + tx * 8);
            p[0] = v0;
            p[1] = v1;
        }
    }
}

// ---------------------------------------------------------------------------
// gather-aggregate layer 1 (fused with mid transform):
// mid[n] = relu( (sum_{e: dst=n} h0[src_e]) * ndst[n] + b1 ) * nsrc[n]
__global__ __launch_bounds__(128) void k_gather1(const float* __restrict__ b1) {
    int node = blockIdx.x;
    int c = threadIdx.x;
    int beg = g_off[node], end = g_off[node + 1];
    float acc0 = 0.0f, acc1 = 0.0f;
    int i = beg;
    for (; i + 1 < end; i += 2) {
        int s0 = __ldg(&g_eidx[i]);
        int s1 = __ldg(&g_eidx[i + 1]);
        acc0 += g_h0[(size_t)s0 * D_HID + c];
        acc1 += g_h0[(size_t)s1 * D_HID + c];
    }
    if (i < end) acc0 += g_h0[(size_t)__ldg(&g_eidx[i]) * D_HID + c];
    float v = (acc0 + acc1) * g_ndst[node] + __ldg(&b1[c]);
    g_mid[(size_t)node * D_HID + c] = fmaxf(v, 0.0f) * g_nsrc[node];
}

// ---------------------------------------------------------------------------
// GEMM2: g_h1[50000,40] = g_mid[50000,128] @ W2[128,40]
__global__ __launch_bounds__(256) void k_gemm2(const float* __restrict__ W2) {
    __shared__ float w2s[D_HID * D_OUT];   // 20 KB
    __shared__ float hs[32][129];
    const int tid = threadIdx.x;
    const int m0 = blockIdx.x * 32;

    for (int i = tid; i < D_HID * D_OUT; i += 256) w2s[i] = W2[i];
#pragma unroll
    for (int t = 0; t < 16; t++) {
        int idx = tid + t * 256;
        int r = idx >> 7, c = idx & 127;
        int row = m0 + r;
        hs[r][c] = (row < N_NODES) ? g_mid[(size_t)row * D_HID + c] : 0.0f;
    }
    __syncthreads();

    float acc[5] = {0.f, 0.f, 0.f, 0.f, 0.f};
    int rr[5], cc[5];
#pragma unroll
    for (int t = 0; t < 5; t++) {
        int o = tid + t * 256;
        rr[t] = o / D_OUT;
        cc[t] = o - rr[t] * D_OUT;
    }
#pragma unroll 4
    for (int k = 0; k < D_HID; k++) {
#pragma unroll
        for (int t = 0; t < 5; t++)
            acc[t] += hs[rr[t]][k] * w2s[k * D_OUT + cc[t]];
    }
#pragma unroll
    for (int t = 0; t < 5; t++) {
        int row = m0 + rr[t];
        if (row < N_NODES) g_h1[(size_t)row * D_OUT + cc[t]] = acc[t];
    }
}

// gather-aggregate layer 2 (fused with final bias/norm):
// out[n] = (sum_{e: dst=n} h1[src_e]) * ndst[n] + b2
__global__ __launch_bounds__(64) void k_gather2(float* __restrict__ out,
                                                const float* __restrict__ b2) {
    int node = blockIdx.x;
    int c = threadIdx.x;
    if (c >= D_OUT) return;
    int beg = g_off[node], end = g_off[node + 1];
    float acc0 = 0.0f, acc1 = 0.0f;
    int i = beg;
    for (; i + 1 < end; i += 2) {
        int s0 = __ldg(&g_eidx[i]);
        int s1 = __ldg(&g_eidx[i + 1]);
        acc0 += g_h1[(size_t)s0 * D_OUT + c];
        acc1 += g_h1[(size_t)s1 * D_OUT + c];
    }
    if (i < end) acc0 += g_h1[(size_t)__ldg(&g_eidx[i]) * D_OUT + c];
    out[(size_t)node * D_OUT + c] = (acc0 + acc1) * g_ndst[node] + __ldg(&b2[c]);
}

// ---------------------------------------------------------------------------
extern "C" void kernel_launch(void* const* d_in, const int* in_sizes, int n_in,
                              void* d_out, int out_size) {
    const float* x   = (const float*)d_in[0];
    const float* W1  = (const float*)d_in[1];
    const float* b1  = (const float*)d_in[2];
    const float* W2  = (const float*)d_in[3];
    const float* b2  = (const float*)d_in[4];
    const int* esrc  = (const int*)d_in[5];
    const int* edst  = (const int*)d_in[6];
    float* out = (float*)d_out;

    const int T = 256;

    // CSR build + norms (parallel scan)
    k_init<<<(N_NODES + T - 1) / T, T>>>();
    k_hist<<<(N_EDGES + T - 1) / T, T>>>(esrc, edst);
    k_part<<<N_PART, SCAN_BLK>>>();
    k_scanpart<<<1, 256>>>();
    k_apply<<<N_PART, SCAN_BLK>>>();
    k_fill<<<(N_EDGES + T - 1) / T, T>>>(esrc, edst);

    // layer 1
    k_gemm1<<<(N_NODES + 127) / 128, 256>>>(x, W1);
    k_gather1<<<N_NODES, 128>>>(b1);

    // layer 2
    k_gemm2<<<(N_NODES + 31) / 32, 256>>>(W2);
    k_gather2<<<N_NODES, 64>>>(out, b2);
}

// round 4
// speedup vs baseline: 3.3619x; 1.4097x over previous
#include <cuda_runtime.h>

#define N_NODES 50000
#define N_EDGES 800000
#define D_IN    256
#define D_HID   128
#define D_OUT   40

#define SCAN_BLK 256
#define N_PART   ((N_NODES + SCAN_BLK - 1) / SCAN_BLK)   // 196

// ---- persistent scratch (no allocations allowed) ----
__device__ int   g_cnt_in [N_NODES];
__device__ int   g_cnt_out[N_NODES];
__device__ int   g_part   [N_PART];
__device__ int   g_pscan  [N_PART];
__device__ int   g_off    [N_NODES + 1];
__device__ int   g_cursor [N_NODES];
__device__ int   g_eidx   [N_EDGES];           // src indices grouped by dst (CSR)
__device__ float g_nsrc   [N_NODES];
__device__ float g_ndst   [N_NODES];
__device__ float g_h0  [(size_t)N_NODES * D_HID];   // (x*nsrc)@W1
__device__ float g_mid [(size_t)N_NODES * D_HID];   // relu(agg*ndst+b1)*nsrc
__device__ float g_h1  [(size_t)N_NODES * D_OUT];   // mid@W2

// ---------------------------------------------------------------------------
__global__ void k_init() {
    int i = blockIdx.x * blockDim.x + threadIdx.x;
    if (i < N_NODES) { g_cnt_in[i] = 0; g_cnt_out[i] = 0; }
}

__global__ void k_hist(const int* __restrict__ src, const int* __restrict__ dst) {
    int i = blockIdx.x * blockDim.x + threadIdx.x;
    if (i < N_EDGES) {
        atomicAdd(&g_cnt_out[src[i]], 1);
        atomicAdd(&g_cnt_in [dst[i]], 1);
    }
}

// phase 1: per-block sums of cnt_in
__global__ __launch_bounds__(SCAN_BLK) void k_part() {
    __shared__ int sh[SCAN_BLK];
    int idx = blockIdx.x * SCAN_BLK + threadIdx.x;
    int v = (idx < N_NODES) ? g_cnt_in[idx] : 0;
    sh[threadIdx.x] = v;
    __syncthreads();
    for (int off = SCAN_BLK / 2; off > 0; off >>= 1) {
        if (threadIdx.x < off) sh[threadIdx.x] += sh[threadIdx.x + off];
        __syncthreads();
    }
    if (threadIdx.x == 0) g_part[blockIdx.x] = sh[0];
}

// phase 2: exclusive scan of the N_PART partials (single small block)
__global__ __launch_bounds__(256) void k_scanpart() {
    __shared__ int sh[256];
    int t = threadIdx.x;
    sh[t] = (t < N_PART) ? g_part[t] : 0;
    __syncthreads();
    for (int off = 1; off < 256; off <<= 1) {
        int v = 0;
        if (t >= off) v = sh[t - off];
        __syncthreads();
        if (t >= off) sh[t] += v;
        __syncthreads();
    }
    if (t < N_PART) g_pscan[t] = (t > 0) ? sh[t - 1] : 0;   // exclusive
    if (t == 0) g_off[N_NODES] = N_EDGES;
}

// phase 3: in-block exclusive scan + block offset -> g_off/g_cursor; fused norms
__global__ __launch_bounds__(SCAN_BLK) void k_apply() {
    __shared__ int sh[SCAN_BLK];
    int t = threadIdx.x;
    int idx = blockIdx.x * SCAN_BLK + t;
    int cin = (idx < N_NODES) ? g_cnt_in[idx] : 0;
    sh[t] = cin;
    __syncthreads();
    for (int off = 1; off < SCAN_BLK; off <<= 1) {
        int v = 0;
        if (t >= off) v = sh[t - off];
        __syncthreads();
        if (t >= off) sh[t] += v;
        __syncthreads();
    }
    if (idx < N_NODES) {
        int excl = sh[t] - cin + g_pscan[blockIdx.x];
        g_off[idx] = excl;
        g_cursor[idx] = excl;
        g_nsrc[idx] = rsqrtf(fmaxf((float)g_cnt_out[idx], 1.0f));
        g_ndst[idx] = rsqrtf(fmaxf((float)cin, 1.0f));
    }
}

__global__ void k_fill(const int* __restrict__ src, const int* __restrict__ dst) {
    int i = blockIdx.x * blockDim.x + threadIdx.x;
    if (i < N_EDGES) {
        int d = dst[i];
        int pos = atomicAdd(&g_cursor[d], 1);
        g_eidx[pos] = src[i];
    }
}

// ---------------------------------------------------------------------------
// GEMM1: g_h0[50000,128] = (x * nsrc[:,None]) @ W1[256,128]
// 128x128x16 tile, 256 threads, 8x8 micro-tile, float4 everywhere.
__global__ __launch_bounds__(256) void k_gemm1(const float* __restrict__ x,
                                               const float* __restrict__ W1) {
    __shared__ float As[16][132];   // transposed A tile [k][row]
    __shared__ float Bs[16][128];   // [k][col]
    const int tid = threadIdx.x;
    const int tx = tid & 15;        // 0..15 -> 8 cols each
    const int ty = tid >> 4;        // 0..15 -> 8 rows each
    const int m0 = blockIdx.x * 128;

    float acc[8][8];
#pragma unroll
    for (int i = 0; i < 8; i++)
#pragma unroll
        for (int j = 0; j < 8; j++) acc[i][j] = 0.0f;

    for (int k0 = 0; k0 < D_IN; k0 += 16) {
        // load A tile (128 rows x 16 k), scaled by nsrc, stored transposed
#pragma unroll
        for (int t = 0; t < 2; t++) {
            int idx = tid + t * 256;      // 0..511
            int r = idx >> 2;             // row 0..127
            int kq = idx & 3;             // float4 within the 16 k's
            int row = m0 + r;
            float4 v = make_float4(0.f, 0.f, 0.f, 0.f);
            float s = 0.0f;
            if (row < N_NODES) {
                v = reinterpret_cast<const float4*>(x + (size_t)row * D_IN + k0)[kq];
                s = g_nsrc[row];
            }
            As[kq * 4 + 0][r] = v.x * s;
            As[kq * 4 + 1][r] = v.y * s;
            As[kq * 4 + 2][r] = v.z * s;
            As[kq * 4 + 3][r] = v.w * s;
        }
        // load B tile (16 k x 128 cols)
#pragma unroll
        for (int t = 0; t < 2; t++) {
            int idx = tid + t * 256;      // 0..511
            int r = idx >> 5;             // k row 0..15
            int c4 = idx & 31;            // float4 col
            float4 w = reinterpret_cast<const float4*>(W1 + (size_t)(k0 + r) * D_HID)[c4];
            reinterpret_cast<float4*>(&Bs[r][c4 * 4])[0] = w;
        }
        __syncthreads();
#pragma unroll
        for (int kk = 0; kk < 16; kk++) {
            float a[8], b[8];
#pragma unroll
            for (int i = 0; i < 8; i++) a[i] = As[kk][ty * 8 + i];
#pragma unroll
            for (int j = 0; j < 8; j++) b[j] = Bs[kk][tx * 8 + j];
#pragma unroll
            for (int i = 0; i < 8; i++)
#pragma unroll
                for (int j = 0; j < 8; j++) acc[i][j] += a[i] * b[j];
        }
        __syncthreads();
    }
#pragma unroll
    for (int i = 0; i < 8; i++) {
        int row = m0 + ty * 8 + i;
        if (row < N_NODES) {
            float4 v0 = make_float4(acc[i][0], acc[i][1], acc[i][2], acc[i][3]);
            float4 v1 = make_float4(acc[i][4], acc[i][5], acc[i][6], acc[i][7]);
            float4* p = reinterpret_cast<float4*>(g_h0 + (size_t)row * D_HID + tx * 8);
            p[0] = v0;
            p[1] = v1;
        }
    }
}

// ---------------------------------------------------------------------------
// gather-aggregate layer 1 (fused with mid transform), warp-per-node, float4:
// mid[n] = relu( (sum_{e: dst=n} h0[src_e]) * ndst[n] + b1 ) * nsrc[n]
__global__ __launch_bounds__(256) void k_gather1(const float* __restrict__ b1) {
    const int warp = threadIdx.x >> 5;
    const int lane = threadIdx.x & 31;
    const int node = blockIdx.x * 8 + warp;
    if (node >= N_NODES) return;
    const int beg = g_off[node], end = g_off[node + 1];
    const float4* __restrict__ h0 = reinterpret_cast<const float4*>(g_h0);

    float4 a0 = make_float4(0.f, 0.f, 0.f, 0.f);
    float4 a1 = make_float4(0.f, 0.f, 0.f, 0.f);
    int i = beg;
    for (; i + 1 < end; i += 2) {
        int s0 = __ldg(&g_eidx[i]);
        int s1 = __ldg(&g_eidx[i + 1]);
        float4 v0 = h0[(size_t)s0 * 32 + lane];
        float4 v1 = h0[(size_t)s1 * 32 + lane];
        a0.x += v0.x; a0.y += v0.y; a0.z += v0.z; a0.w += v0.w;
        a1.x += v1.x; a1.y += v1.y; a1.z += v1.z; a1.w += v1.w;
    }
    if (i < end) {
        int s0 = __ldg(&g_eidx[i]);
        float4 v0 = h0[(size_t)s0 * 32 + lane];
        a0.x += v0.x; a0.y += v0.y; a0.z += v0.z; a0.w += v0.w;
    }
    const float nd = g_ndst[node];
    const float ns = g_nsrc[node];
    const float4 bb = reinterpret_cast<const float4*>(b1)[lane];
    float4 r;
    r.x = fmaxf((a0.x + a1.x) * nd + bb.x, 0.0f) * ns;
    r.y = fmaxf((a0.y + a1.y) * nd + bb.y, 0.0f) * ns;
    r.z = fmaxf((a0.z + a1.z) * nd + bb.z, 0.0f) * ns;
    r.w = fmaxf((a0.w + a1.w) * nd + bb.w, 0.0f) * ns;
    reinterpret_cast<float4*>(g_mid)[(size_t)node * 32 + lane] = r;
}

// ---------------------------------------------------------------------------
// GEMM2: g_h1[50000,40] = g_mid[50000,128] @ W2[128,40]
// 128-row tile, 256 threads, 4x5 micro-tile, k chunked by 16 (transposed smem).
__global__ __launch_bounds__(256) void k_gemm2(const float* __restrict__ W2) {
    __shared__ float w2s[D_HID * D_OUT];   // 20 KB, [k][40]
    __shared__ float hs_t[16][132];        // transposed chunk [k][row], 16B-aligned rows
    const int tid = threadIdx.x;
    const int ry = tid >> 3;               // 0..31 -> 4 rows each
    const int cx = tid & 7;                // 0..7  -> 5 cols each
    const int m0 = blockIdx.x * 128;

    for (int i = tid; i < D_HID * D_OUT; i += 256) w2s[i] = W2[i];

    float acc[4][5];
#pragma unroll
    for (int i = 0; i < 4; i++)
#pragma unroll
        for (int j = 0; j < 5; j++) acc[i][j] = 0.0f;

    for (int k0 = 0; k0 < D_HID; k0 += 16) {
        __syncthreads();
        // load 128 rows x 16 k chunk of g_mid, transposed into hs_t
#pragma unroll
        for (int t = 0; t < 2; t++) {
            int idx = tid + t * 256;       // 0..511
            int r = idx >> 2;              // row 0..127
            int f4 = idx & 3;              // which float4 within 16 k's
            int row = m0 + r;
            float4 v = make_float4(0.f, 0.f, 0.f, 0.f);
            if (row < N_NODES)
                v = reinterpret_cast<const float4*>(g_mid + (size_t)row * D_HID + k0)[f4];
            hs_t[f4 * 4 + 0][r] = v.x;
            hs_t[f4 * 4 + 1][r] = v.y;
            hs_t[f4 * 4 + 2][r] = v.z;
            hs_t[f4 * 4 + 3][r] = v.w;
        }
        __syncthreads();
#pragma unroll
        for (int kk = 0; kk < 16; kk++) {
            float4 a = reinterpret_cast<const float4*>(&hs_t[kk][0])[ry];
            float b[5];
#pragma unroll
            for (int j = 0; j < 5; j++) b[j] = w2s[(k0 + kk) * D_OUT + cx * 5 + j];
#pragma unroll
            for (int j = 0; j < 5; j++) {
                acc[0][j] += a.x * b[j];
                acc[1][j] += a.y * b[j];
                acc[2][j] += a.z * b[j];
                acc[3][j] += a.w * b[j];
            }
        }
    }
#pragma unroll
    for (int i = 0; i < 4; i++) {
        int row = m0 + ry * 4 + i;
        if (row < N_NODES) {
#pragma unroll
            for (int j = 0; j < 5; j++)
                g_h1[(size_t)row * D_OUT + cx * 5 + j] = acc[i][j];
        }
    }
}

// gather-aggregate layer 2 (fused with final bias/norm), 40 threads per node:
// out[n] = (sum_{e: dst=n} h1[src_e]) * ndst[n] + b2
__global__ __launch_bounds__(240) void k_gather2(float* __restrict__ out,
                                                 const float* __restrict__ b2) {
    const int local = threadIdx.x / D_OUT;        // 0..5
    const int c     = threadIdx.x - local * D_OUT; // 0..39
    const int node  = blockIdx.x * 6 + local;
    if (node >= N_NODES) return;
    const int beg = g_off[node], end = g_off[node + 1];
    float acc0 = 0.0f, acc1 = 0.0f;
    int i = beg;
    for (; i + 1 < end; i += 2) {
        int s0 = __ldg(&g_eidx[i]);
        int s1 = __ldg(&g_eidx[i + 1]);
        acc0 += g_h1[(size_t)s0 * D_OUT + c];
        acc1 += g_h1[(size_t)s1 * D_OUT + c];
    }
    if (i < end) acc0 += g_h1[(size_t)__ldg(&g_eidx[i]) * D_OUT + c];
    out[(size_t)node * D_OUT + c] = (acc0 + acc1) * g_ndst[node] + __ldg(&b2[c]);
}

// ---------------------------------------------------------------------------
extern "C" void kernel_launch(void* const* d_in, const int* in_sizes, int n_in,
                              void* d_out, int out_size) {
    const float* x   = (const float*)d_in[0];
    const float* W1  = (const float*)d_in[1];
    const float* b1  = (const float*)d_in[2];
    const float* W2  = (const float*)d_in[3];
    const float* b2  = (const float*)d_in[4];
    const int* esrc  = (const int*)d_in[5];
    const int* edst  = (const int*)d_in[6];
    float* out = (float*)d_out;

    const int T = 256;

    // CSR build + norms (parallel scan)
    k_init<<<(N_NODES + T - 1) / T, T>>>();
    k_hist<<<(N_EDGES + T - 1) / T, T>>>(esrc, edst);
    k_part<<<N_PART, SCAN_BLK>>>();
    k_scanpart<<<1, 256>>>();
    k_apply<<<N_PART, SCAN_BLK>>>();
    k_fill<<<(N_EDGES + T - 1) / T, T>>>(esrc, edst);

    // layer 1
    k_gemm1<<<(N_NODES + 127) / 128, 256>>>(x, W1);
    k_gather1<<<(N_NODES + 7) / 8, 256>>>(b1);

    // layer 2
    k_gemm2<<<(N_NODES + 127) / 128, 256>>>(W2);
    k_gather2<<<(N_NODES + 5) / 6, 240>>>(out, b2);
}